// round 1
// baseline (speedup 1.0000x reference)
#include <cuda_runtime.h>
#include <math.h>

// Problem constants
#define BATCH   4
#define SEQ     4096
#define HID     2048
#define HEADD   256
#define VDIM    512
#define MROWS   (BATCH*SEQ)        // 16384

// log2(0.96875)
#define LOG2_GAMMA (-0.045803686185410744f)

// Scratch (allocation-free rule: __device__ globals)
__device__ float g_Q[(size_t)MROWS * HEADD];   // 16 MB
__device__ float g_K[(size_t)MROWS * HEADD];   // 16 MB
__device__ float g_V[(size_t)MROWS * VDIM];    // 32 MB

// ---------------------------------------------------------------------------
// Projection GEMM:  C[M,N] = X[M,2048] @ W[2048,N], with optional xPos epilogue
// MODE 0: plain -> g_V ; MODE 1: xPos -> g_Q ; MODE 2: xPos downscale -> g_K
// Tile: BM=128, BN=128, BK=16, 256 threads, 8x8 micro-tile.
// ---------------------------------------------------------------------------
template <int MODE, int N>
__global__ void __launch_bounds__(256, 2) proj_kernel(const float* __restrict__ A,
                                                      const float* __restrict__ W)
{
    __shared__ __align__(16) float As[16][132];   // [k][m], padded
    __shared__ __align__(16) float Bs[16][128];   // [k][n]

    const int tid = threadIdx.x;
    const int m0  = blockIdx.y * 128;
    const int n0  = blockIdx.x * 128;

    // global-load mapping
    const int lr  = tid >> 2;          // 0..63   (A rows: lr, lr+64)
    const int lc4 = (tid & 3) * 4;     // 0,4,8,12 (A k-cols)
    const int br  = tid >> 5;          // 0..7    (B rows: br, br+8)
    const int bc  = (tid & 31) * 4;    // 0..124  (B n-cols)

    // compute mapping
    const int row0 = (tid >> 4) * 8;   // 0..120
    const int col0 = (tid & 15) * 8;   // 0..120

    float acc[8][8];
#pragma unroll
    for (int i = 0; i < 8; i++)
#pragma unroll
        for (int j = 0; j < 8; j++) acc[i][j] = 0.0f;

    for (int k0 = 0; k0 < HID; k0 += 16) {
        float4 a0 = *(const float4*)(A + (size_t)(m0 + lr)      * HID + k0 + lc4);
        float4 a1 = *(const float4*)(A + (size_t)(m0 + lr + 64) * HID + k0 + lc4);
        float4 b0 = *(const float4*)(W + (size_t)(k0 + br)     * N + n0 + bc);
        float4 b1 = *(const float4*)(W + (size_t)(k0 + br + 8) * N + n0 + bc);

        As[lc4 + 0][lr] = a0.x;  As[lc4 + 1][lr] = a0.y;
        As[lc4 + 2][lr] = a0.z;  As[lc4 + 3][lr] = a0.w;
        As[lc4 + 0][lr + 64] = a1.x;  As[lc4 + 1][lr + 64] = a1.y;
        As[lc4 + 2][lr + 64] = a1.z;  As[lc4 + 3][lr + 64] = a1.w;
        *(float4*)&Bs[br][bc]     = b0;
        *(float4*)&Bs[br + 8][bc] = b1;
        __syncthreads();

#pragma unroll
        for (int kk = 0; kk < 16; kk++) {
            float av[8], bv[8];
            *(float4*)&av[0] = *(const float4*)&As[kk][row0];
            *(float4*)&av[4] = *(const float4*)&As[kk][row0 + 4];
            *(float4*)&bv[0] = *(const float4*)&Bs[kk][col0];
            *(float4*)&bv[4] = *(const float4*)&Bs[kk][col0 + 4];
#pragma unroll
            for (int i = 0; i < 8; i++)
#pragma unroll
                for (int j = 0; j < 8; j++) acc[i][j] += av[i] * bv[j];
        }
        __syncthreads();
    }

    float* Cout = (MODE == 0) ? g_V : ((MODE == 1) ? g_Q : g_K);

    if (MODE == 0) {
#pragma unroll
        for (int i = 0; i < 8; i++) {
            const int m = m0 + row0 + i;
            *(float4*)&Cout[(size_t)m * N + n0 + col0]     = make_float4(acc[i][0], acc[i][1], acc[i][2], acc[i][3]);
            *(float4*)&Cout[(size_t)m * N + n0 + col0 + 4] = make_float4(acc[i][4], acc[i][5], acc[i][6], acc[i][7]);
        }
    } else {
        // xPos epilogue: pair (2j,2j+1) rotated by theta = s/10000^{j/128},
        // scaled by ((2j+0.4d)/(1.4d))^{s/512} (inverted for K).
#pragma unroll
        for (int i = 0; i < 8; i++) {
            const int m = m0 + row0 + i;
            const float s = (float)(m & (SEQ - 1));
            float res[8];
#pragma unroll
            for (int p = 0; p < 4; p++) {
                const int n = n0 + col0 + p * 2;
                const float jj   = (float)(n >> 1);
                const float invf = 1.0f / powf(10000.0f, jj * (1.0f / 128.0f));
                const float theta = s * invf;
                float sn, cs;
                sincosf(theta, &sn, &cs);
                const float sv = ((float)n + 102.4f) / 358.4f;
                float sc = powf(sv, s * (1.0f / 512.0f));
                if (MODE == 2) sc = 1.0f / sc;
                const float snS = sn * sc, csS = cs * sc;
                const float v0 = acc[i][p * 2], v1 = acc[i][p * 2 + 1];
                res[p * 2]     = v0 * csS - v1 * snS;
                res[p * 2 + 1] = v1 * csS + v0 * snS;
            }
            *(float4*)&Cout[(size_t)m * N + n0 + col0]     = *(float4*)&res[0];
            *(float4*)&Cout[(size_t)m * N + n0 + col0 + 4] = *(float4*)&res[4];
        }
    }
}

// ---------------------------------------------------------------------------
// Fused retention: O[q, v] = sum_{k<=q} gamma^{q-k} (Q_q . K_k) V[k, v]
// Block: (batch b, q-tile of 64, v-half of 256). Flash-style over k-tiles,
// truncated to the 16 most recent k-tiles (gamma^961 ~ 5e-14: negligible).
// ---------------------------------------------------------------------------
__global__ void __launch_bounds__(256, 2) retention_kernel(float* __restrict__ Out)
{
    __shared__ __align__(16) union SmemU {
        float qk[2][32][68];   // [Q|K][d][row]  (phase 1)
        float ss[64][68];      // decayed S, [k][q] (phases 2-3)
    } u;
    __shared__ __align__(16) float Vs[64][68];   // V chunk [k][v]

    const int tid = threadIdx.x;
    const int tx = tid & 15, ty = tid >> 4;
    const int b  = blockIdx.z;
    const int qt = blockIdx.y;
    const int v0 = blockIdx.x * 256;
    const int q0 = qt * 64;
    const int base = b * SEQ;

    float o[4][16];
#pragma unroll
    for (int i = 0; i < 4; i++)
#pragma unroll
        for (int j = 0; j < 16; j++) o[i][j] = 0.0f;

    int kt_lo = qt - 15;
    if (kt_lo < 0) kt_lo = 0;

    for (int kt = kt_lo; kt <= qt; kt++) {
        const int k0 = kt * 64;

        // ---- Phase 1: S = Q_tile @ K_tile^T over d=256 ----
        float sacc[4][4];
#pragma unroll
        for (int i = 0; i < 4; i++)
#pragma unroll
            for (int j = 0; j < 4; j++) sacc[i][j] = 0.0f;

        const int r  = tid >> 3;          // 0..31
        const int c4 = (tid & 7) * 4;     // 0..28

        for (int d0 = 0; d0 < HEADD; d0 += 32) {
            float4 qa = *(const float4*)(g_Q + (size_t)(base + q0 + r)      * HEADD + d0 + c4);
            float4 qb = *(const float4*)(g_Q + (size_t)(base + q0 + r + 32) * HEADD + d0 + c4);
            float4 ka = *(const float4*)(g_K + (size_t)(base + k0 + r)      * HEADD + d0 + c4);
            float4 kb = *(const float4*)(g_K + (size_t)(base + k0 + r + 32) * HEADD + d0 + c4);
            u.qk[0][c4 + 0][r] = qa.x;  u.qk[0][c4 + 1][r] = qa.y;
            u.qk[0][c4 + 2][r] = qa.z;  u.qk[0][c4 + 3][r] = qa.w;
            u.qk[0][c4 + 0][r + 32] = qb.x;  u.qk[0][c4 + 1][r + 32] = qb.y;
            u.qk[0][c4 + 2][r + 32] = qb.z;  u.qk[0][c4 + 3][r + 32] = qb.w;
            u.qk[1][c4 + 0][r] = ka.x;  u.qk[1][c4 + 1][r] = ka.y;
            u.qk[1][c4 + 2][r] = ka.z;  u.qk[1][c4 + 3][r] = ka.w;
            u.qk[1][c4 + 0][r + 32] = kb.x;  u.qk[1][c4 + 1][r + 32] = kb.y;
            u.qk[1][c4 + 2][r + 32] = kb.z;  u.qk[1][c4 + 3][r + 32] = kb.w;
            __syncthreads();

#pragma unroll
            for (int dd = 0; dd < 32; dd++) {
                float4 qv = *(const float4*)&u.qk[0][dd][ty * 4];
                float4 kv = *(const float4*)&u.qk[1][dd][tx * 4];
                float qa4[4] = {qv.x, qv.y, qv.z, qv.w};
                float ka4[4] = {kv.x, kv.y, kv.z, kv.w};
#pragma unroll
                for (int i = 0; i < 4; i++)
#pragma unroll
                    for (int j = 0; j < 4; j++) sacc[i][j] += qa4[i] * ka4[j];
            }
            __syncthreads();
        }

        // ---- Phase 2: decay mask, write S transposed [k][q] ----
#pragma unroll
        for (int i = 0; i < 4; i++) {
#pragma unroll
            for (int j = 0; j < 4; j++) {
                const int dq = (q0 + ty * 4 + i) - (k0 + tx * 4 + j);
                const float dec = (dq >= 0) ? exp2f((float)dq * LOG2_GAMMA) : 0.0f;
                u.ss[tx * 4 + j][ty * 4 + i] = sacc[i][j] * dec;
            }
        }
        __syncthreads();

        // ---- Phase 3: O += S @ V, v in 4 chunks of 64 ----
        for (int vc = 0; vc < 4; vc++) {
#pragma unroll
            for (int uu = 0; uu < 4; uu++) {
                const int vr = (tid >> 4) + uu * 16;
                float4 vv = *(const float4*)(g_V + (size_t)(base + k0 + vr) * VDIM
                                              + v0 + vc * 64 + (tid & 15) * 4);
                *(float4*)&Vs[vr][(tid & 15) * 4] = vv;
            }
            __syncthreads();

#pragma unroll
            for (int kk = 0; kk < 64; kk++) {
                float4 sv = *(const float4*)&u.ss[kk][ty * 4];
                float4 vv = *(const float4*)&Vs[kk][tx * 4];
                float s4[4] = {sv.x, sv.y, sv.z, sv.w};
                float v4[4] = {vv.x, vv.y, vv.z, vv.w};
#pragma unroll
                for (int i = 0; i < 4; i++)
#pragma unroll
                    for (int j = 0; j < 4; j++) o[i][vc * 4 + j] += s4[i] * v4[j];
            }
            __syncthreads();
        }
    }

    // ---- Write output ----
#pragma unroll
    for (int i = 0; i < 4; i++) {
        const size_t rowoff = (size_t)(base + q0 + ty * 4 + i) * VDIM + v0;
#pragma unroll
        for (int vc = 0; vc < 4; vc++) {
            float4 w = make_float4(o[i][vc * 4 + 0], o[i][vc * 4 + 1],
                                   o[i][vc * 4 + 2], o[i][vc * 4 + 3]);
            *(float4*)&Out[rowoff + vc * 64 + tx * 4] = w;
        }
    }
}

// ---------------------------------------------------------------------------
extern "C" void kernel_launch(void* const* d_in, const int* in_sizes, int n_in,
                              void* d_out, int out_size)
{
    const float* X  = (const float*)d_in[0];
    const float* WQ = (const float*)d_in[1];
    const float* WK = (const float*)d_in[2];
    const float* WV = (const float*)d_in[3];
    float* out = (float*)d_out;

    dim3 blk(256);
    proj_kernel<1, HEADD><<<dim3(HEADD / 128, MROWS / 128), blk>>>(X, WQ);
    proj_kernel<2, HEADD><<<dim3(HEADD / 128, MROWS / 128), blk>>>(X, WK);
    proj_kernel<0, VDIM ><<<dim3(VDIM  / 128, MROWS / 128), blk>>>(X, WV);
    retention_kernel<<<dim3(VDIM / 256, SEQ / 64, BATCH), blk>>>(out);
}

// round 3
// speedup vs baseline: 2.2107x; 2.2107x over previous
#include <cuda_runtime.h>
#include <math.h>
#include <stdint.h>

#define BATCH   4
#define SEQ     4096
#define HID     2048
#define HEADD   256
#define VDIM    512
#define MROWS   (BATCH*SEQ)

#define LOG2_GAMMA (-0.045803686185410744f)
#define GAMMA_INV  (1.0322580645161290f)   // 1/0.96875
#define GAMMA_P8   (0.7756998776f)         // 0.96875^8
#define GAMMA_M8   (1.2891590567f)         // 0.96875^-8

// Scratch (__device__ globals: allocation-free rule)
__device__ float g_Q[(size_t)MROWS * HEADD];
__device__ float g_K[(size_t)MROWS * HEADD];
__device__ float g_V[(size_t)MROWS * VDIM];

// ---------------------------------------------------------------------------
// helpers
// ---------------------------------------------------------------------------
__device__ __forceinline__ uint32_t smem_u32(const void* p) {
    uint32_t a;
    asm("{ .reg .u64 t; cvta.to.shared.u64 t, %1; cvt.u32.u64 %0, t; }" : "=r"(a) : "l"(p));
    return a;
}
__device__ __forceinline__ void cp_async16(uint32_t s, const void* g) {
    asm volatile("cp.async.cg.shared.global [%0], [%1], 16;" :: "r"(s), "l"(g) : "memory");
}
#define CP_COMMIT()  asm volatile("cp.async.commit_group;" ::: "memory")
#define CP_WAIT(N)   asm volatile("cp.async.wait_group %0;" :: "n"(N) : "memory")

__device__ __forceinline__ uint32_t f2tf(float x) {
    uint32_t r;
    asm("cvt.rna.tf32.f32 %0, %1;" : "=r"(r) : "f"(x));
    return r;
}
__device__ __forceinline__ void tf_split(float x, uint32_t& hi, uint32_t& lo) {
    hi = f2tf(x);
    lo = f2tf(x - __uint_as_float(hi));
}
__device__ __forceinline__ void mma8(float* d, const uint32_t* a, const uint32_t* b) {
    asm volatile("mma.sync.aligned.m16n8k8.row.col.f32.tf32.tf32.f32 "
                 "{%0,%1,%2,%3},{%4,%5,%6,%7},{%8,%9},{%0,%1,%2,%3};"
                 : "+f"(d[0]), "+f"(d[1]), "+f"(d[2]), "+f"(d[3])
                 : "r"(a[0]), "r"(a[1]), "r"(a[2]), "r"(a[3]), "r"(b[0]), "r"(b[1]));
}
__device__ __forceinline__ void mma3x(float* d, const uint32_t* ah, const uint32_t* al,
                                      const uint32_t* bh, const uint32_t* bl) {
    mma8(d, ah, bh);
    mma8(d, ah, bl);
    mma8(d, al, bh);
}

// ===========================================================================
// Projection: C[M,2048]@W[2048,N], 3xTF32 mma.sync, xPos epilogue.
// CTA tile 128x128, BK=16, 2-stage cp.async. 8 warps (2x4), warp 64x32.
// grid.x = 8 jobs: 0,1=Q  2,3=K  4..7=V (n-tiles of 128)
// ===========================================================================
#define APAD 20
#define BPAD 132

__device__ __forceinline__ void proj_load_stage(uint32_t aB, uint32_t bB,
                                                const float* __restrict__ X,
                                                const float* __restrict__ W,
                                                int N, int n0, int m0, int k0, int tid)
{
#pragma unroll
    for (int i = 0; i < 2; i++) {
        int c = tid + i * 256;
        int row = c >> 2, cc = c & 3;
        cp_async16(aB + (uint32_t)(row * APAD + cc * 4) * 4,
                   X + (size_t)(m0 + row) * HID + k0 + cc * 4);
    }
#pragma unroll
    for (int i = 0; i < 2; i++) {
        int c = tid + i * 256;
        int row = c >> 5, cc = c & 31;
        cp_async16(bB + (uint32_t)(row * BPAD + cc * 4) * 4,
                   W + (size_t)(k0 + row) * N + n0 + cc * 4);
    }
    CP_COMMIT();
}

__global__ void __launch_bounds__(256, 1)
proj_mma_kernel(const float* __restrict__ X, const float* __restrict__ WQ,
                const float* __restrict__ WK, const float* __restrict__ WV)
{
    __shared__ __align__(16) float As[2][128 * APAD];
    __shared__ __align__(16) float Bs[2][16 * BPAD];

    const int tid = threadIdx.x, wid = tid >> 5, lane = tid & 31;
    const int g = lane >> 2, tg = lane & 3;
    const int m0 = blockIdx.y * 128;
    const int job = blockIdx.x;

    const float* W; float* dst; int N, n0, mode;
    if (job < 2)      { W = WQ; dst = g_Q; N = HEADD; n0 = job * 128;       mode = 1; }
    else if (job < 4) { W = WK; dst = g_K; N = HEADD; n0 = (job - 2) * 128; mode = 2; }
    else              { W = WV; dst = g_V; N = VDIM;  n0 = (job - 4) * 128; mode = 0; }

    const int wm = (wid >> 2) * 64, wn = (wid & 3) * 32;

    float acc[4][4][4];
#pragma unroll
    for (int a = 0; a < 4; a++)
#pragma unroll
        for (int bb = 0; bb < 4; bb++)
#pragma unroll
            for (int c = 0; c < 4; c++) acc[a][bb][c] = 0.0f;

    proj_load_stage(smem_u32(&As[0][0]), smem_u32(&Bs[0][0]), X, W, N, n0, m0, 0, tid);

    for (int kb = 0; kb < 128; kb++) {
        const int buf = kb & 1;
        if (kb + 1 < 128) {
            proj_load_stage(smem_u32(&As[buf ^ 1][0]), smem_u32(&Bs[buf ^ 1][0]),
                            X, W, N, n0, m0, (kb + 1) * 16, tid);
            CP_WAIT(1);
        } else {
            CP_WAIT(0);
        }
        __syncthreads();

        const float* A = &As[buf][0];
        const float* B = &Bs[buf][0];
#pragma unroll
        for (int ks = 0; ks < 2; ks++) {
            const int kk = ks * 8;
            uint32_t ah[4][4], al[4][4], bh[4][2], bl[4][2];
#pragma unroll
            for (int mf = 0; mf < 4; mf++) {
                const int r0 = wm + mf * 16 + g;
                tf_split(A[r0 * APAD + kk + tg],           ah[mf][0], al[mf][0]);
                tf_split(A[(r0 + 8) * APAD + kk + tg],     ah[mf][1], al[mf][1]);
                tf_split(A[r0 * APAD + kk + tg + 4],       ah[mf][2], al[mf][2]);
                tf_split(A[(r0 + 8) * APAD + kk + tg + 4], ah[mf][3], al[mf][3]);
            }
#pragma unroll
            for (int nf = 0; nf < 4; nf++) {
                const int cl = wn + nf * 8 + g;
                tf_split(B[(kk + tg) * BPAD + cl],     bh[nf][0], bl[nf][0]);
                tf_split(B[(kk + tg + 4) * BPAD + cl], bh[nf][1], bl[nf][1]);
            }
#pragma unroll
            for (int mf = 0; mf < 4; mf++)
#pragma unroll
                for (int nf = 0; nf < 4; nf++)
                    mma3x(acc[mf][nf], ah[mf], al[mf], bh[nf], bl[nf]);
        }
        __syncthreads();
    }

    // epilogue with optional xPos
#pragma unroll
    for (int mf = 0; mf < 4; mf++) {
#pragma unroll
        for (int half = 0; half < 2; half++) {
            const int m = m0 + wm + mf * 16 + g + half * 8;
            const float s = (float)(m & (SEQ - 1));
#pragma unroll
            for (int nf = 0; nf < 4; nf++) {
                const int ncol = wn + nf * 8 + 2 * tg;
                float e = acc[mf][nf][half * 2];
                float o = acc[mf][nf][half * 2 + 1];
                if (mode != 0) {
                    const int nn = n0 + ncol;           // even
                    const float jj = (float)(nn >> 1);
                    const float invf = powf(10000.0f, -jj * (1.0f / 128.0f));
                    float sn, cs;
                    sincosf(s * invf, &sn, &cs);
                    const float sv = ((float)nn + 102.4f) / 358.4f;
                    float sc = powf(sv, s * (1.0f / 512.0f));
                    if (mode == 2) sc = 1.0f / sc;
                    const float snS = sn * sc, csS = cs * sc;
                    const float ne = e * csS - o * snS;
                    const float no = o * csS + e * snS;
                    e = ne; o = no;
                }
                float2 w = make_float2(e, o);
                *(float2*)&dst[(size_t)m * N + n0 + ncol] = w;
            }
        }
    }
}

// ===========================================================================
// Retention: per CTA (vh in {0,1}, qt, b). 64 q-rows x 256 v-cols.
// Q persistent in SMEM; K then V staged through shared KV buffer.
// S = QK^T (3xTF32) -> decay -> SMEM -> O += S@V (3xTF32).
// Window: 16 most recent k-tiles (gamma^961 ~ 5e-14).
// ===========================================================================
#define QKPAD 260
#define SSPAD 68
#define KV_OFF (64 * QKPAD)
#define SS_OFF (2 * 64 * QKPAD)
#define RET_SMEM ((2 * 64 * QKPAD + 64 * SSPAD) * 4)

__device__ __forceinline__ void ret_load_tile(uint32_t sB, const float* __restrict__ src,
                                              int gstride, int tid)
{
#pragma unroll
    for (int i = 0; i < 16; i++) {
        int c = tid + i * 256;
        int row = c >> 6, cc = c & 63;
        cp_async16(sB + (uint32_t)(row * QKPAD + cc * 4) * 4,
                   src + (size_t)row * gstride + cc * 4);
    }
    CP_COMMIT();
}

__global__ void __launch_bounds__(256, 1) retention_mma_kernel(float* __restrict__ Out)
{
    extern __shared__ __align__(16) float sm[];
    float* Qs = sm;
    float* KV = sm + KV_OFF;
    float* Ss = sm + SS_OFF;

    const int tid = threadIdx.x, wid = tid >> 5, lane = tid & 31;
    const int g = lane >> 2, tg = lane & 3;
    const int vh = blockIdx.x, qt = blockIdx.y, b = blockIdx.z;
    const int q0 = qt * 64, base = b * SEQ;

    const int wm = (wid >> 2) * 32;       // q-rows for both phases
    const int wn = (wid & 3) * 16;        // keys (phase 1)
    const int wv = (wid & 3) * 64;        // v-cols (phase 3)

    // load Q tile (persistent)
    ret_load_tile(smem_u32(Qs), g_Q + (size_t)(base + q0) * HEADD, HEADD, tid);

    float o[2][8][4];
#pragma unroll
    for (int a = 0; a < 2; a++)
#pragma unroll
        for (int bb = 0; bb < 8; bb++)
#pragma unroll
            for (int c = 0; c < 4; c++) o[a][bb][c] = 0.0f;

    int kt_lo = qt - 15; if (kt_lo < 0) kt_lo = 0;

    for (int kt = kt_lo; kt <= qt; kt++) {
        const int k0 = kt * 64;

        // ---- load K tile ----
        ret_load_tile(smem_u32(KV), g_K + (size_t)(base + k0) * HEADD, HEADD, tid);
        CP_WAIT(0);
        __syncthreads();

        // ---- S = Q @ K^T (3xTF32) ----
        float s4[2][2][4];
#pragma unroll
        for (int a = 0; a < 2; a++)
#pragma unroll
            for (int bb = 0; bb < 2; bb++)
#pragma unroll
                for (int c = 0; c < 4; c++) s4[a][bb][c] = 0.0f;

#pragma unroll 4
        for (int ks = 0; ks < 32; ks++) {
            const int kk = ks * 8;
            uint32_t ah[2][4], al[2][4], bh[2][2], bl[2][2];
#pragma unroll
            for (int mf = 0; mf < 2; mf++) {
                const int r0 = wm + mf * 16 + g;
                tf_split(Qs[r0 * QKPAD + kk + tg],           ah[mf][0], al[mf][0]);
                tf_split(Qs[(r0 + 8) * QKPAD + kk + tg],     ah[mf][1], al[mf][1]);
                tf_split(Qs[r0 * QKPAD + kk + tg + 4],       ah[mf][2], al[mf][2]);
                tf_split(Qs[(r0 + 8) * QKPAD + kk + tg + 4], ah[mf][3], al[mf][3]);
            }
#pragma unroll
            for (int nf = 0; nf < 2; nf++) {
                const int key = wn + nf * 8 + g;
                tf_split(KV[key * QKPAD + kk + tg],     bh[nf][0], bl[nf][0]);
                tf_split(KV[key * QKPAD + kk + tg + 4], bh[nf][1], bl[nf][1]);
            }
#pragma unroll
            for (int mf = 0; mf < 2; mf++)
#pragma unroll
                for (int nf = 0; nf < 2; nf++)
                    mma3x(s4[mf][nf], ah[mf], al[mf], bh[nf], bl[nf]);
        }

        // ---- decay + store S to SMEM ----
        if (kt < qt) {
#pragma unroll
            for (int mf = 0; mf < 2; mf++) {
                const int q_l = wm + mf * 16 + g;
                const int dq0 = (q0 - k0) + q_l - (wn + 2 * tg);
                const float d00 = exp2f((float)dq0 * LOG2_GAMMA);
#pragma unroll
                for (int nf = 0; nf < 2; nf++) {
                    const int k_l = wn + nf * 8 + 2 * tg;
                    const float dc0 = (nf == 0) ? d00 : d00 * GAMMA_M8;
                    const float dc1 = dc0 * GAMMA_INV;
                    const float dc2 = dc0 * GAMMA_P8;
                    const float dc3 = dc2 * GAMMA_INV;
                    Ss[q_l * SSPAD + k_l]           = s4[mf][nf][0] * dc0;
                    Ss[q_l * SSPAD + k_l + 1]       = s4[mf][nf][1] * dc1;
                    Ss[(q_l + 8) * SSPAD + k_l]     = s4[mf][nf][2] * dc2;
                    Ss[(q_l + 8) * SSPAD + k_l + 1] = s4[mf][nf][3] * dc3;
                }
            }
        } else {
            // diagonal tile: per-element mask
#pragma unroll
            for (int mf = 0; mf < 2; mf++) {
                const int q_l = wm + mf * 16 + g;
#pragma unroll
                for (int nf = 0; nf < 2; nf++) {
                    const int k_l = wn + nf * 8 + 2 * tg;
#pragma unroll
                    for (int c = 0; c < 4; c++) {
                        const int qq = q_l + (c >> 1) * 8;
                        const int kk2 = k_l + (c & 1);
                        const int dq = qq - kk2;
                        const float dec = (dq >= 0) ? exp2f((float)dq * LOG2_GAMMA) : 0.0f;
                        Ss[qq * SSPAD + kk2] = s4[mf][nf][c] * dec;
                    }
                }
            }
        }
        __syncthreads();   // K reads + Ss writes complete

        // ---- load V tile into KV ----
        ret_load_tile(smem_u32(KV), g_V + (size_t)(base + k0) * VDIM + vh * 256, VDIM, tid);
        CP_WAIT(0);
        __syncthreads();

        // ---- O += S @ V (3xTF32) ----
#pragma unroll
        for (int ks = 0; ks < 8; ks++) {
            const int kk = ks * 8;
            uint32_t ah[2][4], al[2][4], bh[8][2], bl[8][2];
#pragma unroll
            for (int mf = 0; mf < 2; mf++) {
                const int r0 = wm + mf * 16 + g;
                tf_split(Ss[r0 * SSPAD + kk + tg],           ah[mf][0], al[mf][0]);
                tf_split(Ss[(r0 + 8) * SSPAD + kk + tg],     ah[mf][1], al[mf][1]);
                tf_split(Ss[r0 * SSPAD + kk + tg + 4],       ah[mf][2], al[mf][2]);
                tf_split(Ss[(r0 + 8) * SSPAD + kk + tg + 4], ah[mf][3], al[mf][3]);
            }
#pragma unroll
            for (int nf = 0; nf < 8; nf++) {
                const int v = wv + nf * 8 + g;
                tf_split(KV[(kk + tg) * QKPAD + v],     bh[nf][0], bl[nf][0]);
                tf_split(KV[(kk + tg + 4) * QKPAD + v], bh[nf][1], bl[nf][1]);
            }
#pragma unroll
            for (int mf = 0; mf < 2; mf++)
#pragma unroll
                for (int nf = 0; nf < 8; nf++)
                    mma3x(o[mf][nf], ah[mf], al[mf], bh[nf], bl[nf]);
        }
        __syncthreads();   // protect KV/Ss for next iteration
    }

    // ---- store O ----
#pragma unroll
    for (int mf = 0; mf < 2; mf++) {
        const int q_l = wm + mf * 16 + g;
#pragma unroll
        for (int nf = 0; nf < 8; nf++) {
            const size_t r0 = (size_t)(base + q0 + q_l) * VDIM + vh * 256 + wv + nf * 8 + 2 * tg;
            *(float2*)&Out[r0]            = make_float2(o[mf][nf][0], o[mf][nf][1]);
            *(float2*)&Out[r0 + 8 * VDIM] = make_float2(o[mf][nf][2], o[mf][nf][3]);
        }
    }
}

// ===========================================================================
extern "C" void kernel_launch(void* const* d_in, const int* in_sizes, int n_in,
                              void* d_out, int out_size)
{
    const float* X  = (const float*)d_in[0];
    const float* WQ = (const float*)d_in[1];
    const float* WK = (const float*)d_in[2];
    const float* WV = (const float*)d_in[3];
    float* out = (float*)d_out;

    cudaFuncSetAttribute(retention_mma_kernel,
                         cudaFuncAttributeMaxDynamicSharedMemorySize, RET_SMEM);

    proj_mma_kernel<<<dim3(8, MROWS / 128), 256>>>(X, WQ, WK, WV);
    retention_mma_kernel<<<dim3(2, SEQ / 64, BATCH), 256, RET_SMEM>>>(out);
}

// round 4
// speedup vs baseline: 5.4943x; 2.4854x over previous
#include <cuda_runtime.h>
#include <cuda_fp16.h>
#include <math.h>
#include <stdint.h>

#define BATCH   4
#define SEQ     4096
#define HID     2048
#define HEADD   256
#define VDIM    512
#define MROWS   (BATCH*SEQ)

#define LOG2_GAMMA (-0.045803686185410744f)
#define GAMMA_INV  (1.0322580645161290f)
#define GAMMA_P8   (0.7756998776f)
#define GAMMA_M8   (1.2891590567f)
#define WINDOW     10

// Scratch (__device__ globals: allocation-free rule)
__device__ float  g_Q [(size_t)MROWS * HEADD];   // rotation only (no xPos scale)
__device__ float  g_K [(size_t)MROWS * HEADD];   // rotation only
__device__ __half g_Vh[(size_t)MROWS * VDIM];    // V*64 hi plane
__device__ __half g_Vl[(size_t)MROWS * VDIM];    // V*64 lo plane

// ---------------------------------------------------------------------------
// helpers
// ---------------------------------------------------------------------------
__device__ __forceinline__ uint32_t smem_u32(const void* p) {
    uint32_t a;
    asm("{ .reg .u64 t; cvta.to.shared.u64 t, %1; cvt.u32.u64 %0, t; }" : "=r"(a) : "l"(p));
    return a;
}
__device__ __forceinline__ void cp_async16(uint32_t s, const void* g) {
    asm volatile("cp.async.cg.shared.global [%0], [%1], 16;" :: "r"(s), "l"(g) : "memory");
}
#define CP_COMMIT()  asm volatile("cp.async.commit_group;" ::: "memory")
#define CP_WAIT(N)   asm volatile("cp.async.wait_group %0;" :: "n"(N) : "memory")

__device__ __forceinline__ void ldm_x4(uint32_t* r, uint32_t a) {
    asm volatile("ldmatrix.sync.aligned.m8n8.x4.shared.b16 {%0,%1,%2,%3}, [%4];"
                 : "=r"(r[0]), "=r"(r[1]), "=r"(r[2]), "=r"(r[3]) : "r"(a));
}
__device__ __forceinline__ void ldm_x2(uint32_t* r, uint32_t a) {
    asm volatile("ldmatrix.sync.aligned.m8n8.x2.shared.b16 {%0,%1}, [%2];"
                 : "=r"(r[0]), "=r"(r[1]) : "r"(a));
}
__device__ __forceinline__ void ldm_x2t(uint32_t* r, uint32_t a) {
    asm volatile("ldmatrix.sync.aligned.m8n8.x2.trans.shared.b16 {%0,%1}, [%2];"
                 : "=r"(r[0]), "=r"(r[1]) : "r"(a));
}
__device__ __forceinline__ void mma16(float* d, const uint32_t* a, const uint32_t* b) {
    asm volatile("mma.sync.aligned.m16n8k16.row.col.f32.f16.f16.f32 "
                 "{%0,%1,%2,%3},{%4,%5,%6,%7},{%8,%9},{%0,%1,%2,%3};"
                 : "+f"(d[0]), "+f"(d[1]), "+f"(d[2]), "+f"(d[3])
                 : "r"(a[0]), "r"(a[1]), "r"(a[2]), "r"(a[3]), "r"(b[0]), "r"(b[1]));
}
__device__ __forceinline__ void mma3(float* d, const uint32_t* ah, const uint32_t* al,
                                     const uint32_t* bh, const uint32_t* bl) {
    mma16(d, ah, bh);
    mma16(d, ah, bl);
    mma16(d, al, bh);
}
__device__ __forceinline__ void hsplit(float x, __half& hi, __half& lo) {
    hi = __float2half_rn(x);
    lo = __float2half_rn(x - __half2float(hi));
}

// ===========================================================================
// Projection: 3xFP16 mma.sync, split-once into SMEM fp16 planes, ldmatrix.
// CTA 128x128, BK=32, reg-prefetch double buffer. 8 warps (2x4), warp 64x32.
// jobs: 0,1=Q  2,3=K  4..7=V. Q/K epilogue: rotation ONLY (scale -> retention).
// V epilogue: x64, split to g_Vh/g_Vl.
// ===========================================================================
#define PA 40     // A plane pitch (halfs): 80B rows, ldmatrix conflict-free
#define PB 136    // B plane pitch (halfs): 272B rows
#define APL(buf, pl) (((buf) * 2 + (pl)) * 128 * PA)
#define BPL(buf, pl) (4 * 128 * PA + ((buf) * 2 + (pl)) * 32 * PB)
#define PROJ_SMEM ((4 * 128 * PA + 4 * 32 * PB) * 2)

__global__ void __launch_bounds__(256, 1)
proj_kernel(const float* __restrict__ X, const float* __restrict__ WQ,
            const float* __restrict__ WK, const float* __restrict__ WV)
{
    extern __shared__ __align__(16) __half sm[];
    const uint32_t sb = smem_u32(sm);

    const int tid = threadIdx.x, wid = tid >> 5, lane = tid & 31;
    const int g = lane >> 2, tg = lane & 3;
    const int m0 = blockIdx.y * 128;
    const int job = blockIdx.x;

    const float* W; int N, n0, mode;
    if (job < 2)      { W = WQ; N = HEADD; n0 = job * 128;       mode = 1; }
    else if (job < 4) { W = WK; N = HEADD; n0 = (job - 2) * 128; mode = 1; }
    else              { W = WV; N = VDIM;  n0 = (job - 4) * 128; mode = 0; }

    const int wm = (wid >> 2) * 64, wn = (wid & 3) * 32;

    // load mappings (fixed per thread)
    int ar[4], ac[4], br[4], bc[4];
#pragma unroll
    for (int i = 0; i < 4; i++) {
        int idx = tid + i * 256;
        ar[i] = idx >> 3;  ac[i] = (idx & 7) * 4;
        br[i] = idx >> 5;  bc[i] = (idx & 31) * 4;
    }

    float acc[4][4][4];
#pragma unroll
    for (int a = 0; a < 4; a++)
#pragma unroll
        for (int b = 0; b < 4; b++)
#pragma unroll
            for (int c = 0; c < 4; c++) acc[a][b][c] = 0.0f;

    float4 ra[4], rb[4];
    auto ldg_blk = [&](int k0) {
#pragma unroll
        for (int i = 0; i < 4; i++) {
            ra[i] = *(const float4*)(X + (size_t)(m0 + ar[i]) * HID + k0 + ac[i]);
            rb[i] = *(const float4*)(W + (size_t)(k0 + br[i]) * N + n0 + bc[i]);
        }
    };
    auto sts_blk = [&](int buf) {
#pragma unroll
        for (int i = 0; i < 4; i++) {
            __half h[4], l[4];
            hsplit(ra[i].x, h[0], l[0]); hsplit(ra[i].y, h[1], l[1]);
            hsplit(ra[i].z, h[2], l[2]); hsplit(ra[i].w, h[3], l[3]);
            __half* ph = sm + APL(buf, 0) + ar[i] * PA + ac[i];
            __half* pl = sm + APL(buf, 1) + ar[i] * PA + ac[i];
            *(__half2*)(ph)     = __halves2half2(h[0], h[1]);
            *(__half2*)(ph + 2) = __halves2half2(h[2], h[3]);
            *(__half2*)(pl)     = __halves2half2(l[0], l[1]);
            *(__half2*)(pl + 2) = __halves2half2(l[2], l[3]);
            hsplit(rb[i].x * 1024.0f, h[0], l[0]); hsplit(rb[i].y * 1024.0f, h[1], l[1]);
            hsplit(rb[i].z * 1024.0f, h[2], l[2]); hsplit(rb[i].w * 1024.0f, h[3], l[3]);
            ph = sm + BPL(buf, 0) + br[i] * PB + bc[i];
            pl = sm + BPL(buf, 1) + br[i] * PB + bc[i];
            *(__half2*)(ph)     = __halves2half2(h[0], h[1]);
            *(__half2*)(ph + 2) = __halves2half2(h[2], h[3]);
            *(__half2*)(pl)     = __halves2half2(l[0], l[1]);
            *(__half2*)(pl + 2) = __halves2half2(l[2], l[3]);
        }
    };

    ldg_blk(0);
    sts_blk(0);
    __syncthreads();

    const int arow_f = lane & 15;                 // ldmatrix A row within 16
    const int acol_f = (lane >> 4) << 3;          // ldmatrix A col offset
    const int brow_f = (lane & 7) + ((lane >> 3) & 1) * 8;

    for (int kb = 0; kb < 64; kb++) {
        const int buf = kb & 1;
        if (kb < 63) ldg_blk((kb + 1) * 32);

#pragma unroll
        for (int k2 = 0; k2 < 2; k2++) {
            const int kk = k2 * 16;
            uint32_t ah[4][4], al[4][4], bh[4][2], bl[4][2];
#pragma unroll
            for (int mf = 0; mf < 4; mf++) {
                const uint32_t off = (uint32_t)((wm + mf * 16 + arow_f) * PA + kk + acol_f) * 2;
                ldm_x4(ah[mf], sb + (uint32_t)APL(buf, 0) * 2 + off);
                ldm_x4(al[mf], sb + (uint32_t)APL(buf, 1) * 2 + off);
            }
#pragma unroll
            for (int nf = 0; nf < 4; nf++) {
                const uint32_t off = (uint32_t)((kk + brow_f) * PB + wn + nf * 8) * 2;
                ldm_x2t(bh[nf], sb + (uint32_t)BPL(buf, 0) * 2 + off);
                ldm_x2t(bl[nf], sb + (uint32_t)BPL(buf, 1) * 2 + off);
            }
#pragma unroll
            for (int mf = 0; mf < 4; mf++)
#pragma unroll
                for (int nf = 0; nf < 4; nf++)
                    mma3(acc[mf][nf], ah[mf], al[mf], bh[nf], bl[nf]);
        }
        if (kb < 63) sts_blk(buf ^ 1);
        __syncthreads();
    }

    // ---- epilogue ----
#pragma unroll
    for (int mf = 0; mf < 4; mf++) {
#pragma unroll
        for (int half = 0; half < 2; half++) {
            const int m = m0 + wm + mf * 16 + g + half * 8;
            const float s = (float)(m & (SEQ - 1));
#pragma unroll
            for (int nf = 0; nf < 4; nf++) {
                const int ncol = wn + nf * 8 + 2 * tg;
                float e = acc[mf][nf][half * 2]     * (1.0f / 1024.0f);
                float o = acc[mf][nf][half * 2 + 1] * (1.0f / 1024.0f);
                if (mode == 1) {
                    // rotation only
                    const int nn = n0 + ncol;
                    const float jj = (float)(nn >> 1);
                    const float invf = powf(10000.0f, -jj * (1.0f / 128.0f));
                    float sn, cs;
                    sincosf(s * invf, &sn, &cs);
                    const float ne = e * cs - o * sn;
                    const float no = o * cs + e * sn;
                    float* dst = (job < 2) ? g_Q : g_K;
                    *(float2*)&dst[(size_t)m * HEADD + n0 + ncol] = make_float2(ne, no);
                } else {
                    // V: x64, split planes
                    __half eh, el, oh, ol;
                    hsplit(e * 64.0f, eh, el);
                    hsplit(o * 64.0f, oh, ol);
                    *(__half2*)&g_Vh[(size_t)m * VDIM + n0 + ncol] = __halves2half2(eh, oh);
                    *(__half2*)&g_Vl[(size_t)m * VDIM + n0 + ncol] = __halves2half2(el, ol);
                }
            }
        }
    }
}

// ===========================================================================
// Retention: per CTA (qt, b): 64 q x 512 v. 3xFP16.
// Q̃ = Qrot * sv^{(q-q0)/512} * 64 ; K̃ = Krot * sv^{(q0-k)/512} * 64  (exact rebalance)
// S_w = (Q̃K̃) * gamma^{q-k} ; O = S_w @ Ṽ / 262144.
// V streamed as 4 x 128-col fp16-plane chunks via double-buffered cp.async.
// ===========================================================================
#define QP 264
#define PS 72
#define PV 136
#define OFF_QH 0
#define OFF_QL (64 * QP)
#define OFF_KH (2 * 64 * QP)
#define OFF_KL (3 * 64 * QP)
#define OFF_SH (4 * 64 * QP)
#define OFF_SL (OFF_SH + 64 * PS)
#define OFF_VB (OFF_SH + 2 * 64 * PS)
#define VPL(buf, pl) (OFF_VB + ((buf) * 2 + (pl)) * 64 * PV)
#define RET_SMEM ((OFF_VB + 4 * 64 * PV) * 2)

__global__ void __launch_bounds__(256, 1) retention_kernel(float* __restrict__ Out)
{
    extern __shared__ __align__(16) __half sm[];
    const uint32_t sb = smem_u32(sm);

    const int tid = threadIdx.x, wid = tid >> 5, lane = tid & 31;
    const int g = lane >> 2, tg = lane & 3;
    const int qt = blockIdx.x, b = blockIdx.y;
    const int q0 = qt * 64, base = b * SEQ;

    const int wm  = (wid >> 2) * 32;    // q rows (both phases)
    const int wn  = (wid & 3) * 16;     // keys (QK)
    const int wvc = (wid & 3) * 32;     // v cols within 128-chunk (PV)

    const int arow_f = lane & 15;
    const int acol_f = (lane >> 4) << 3;
    const int brow_f = (lane & 7) + ((lane >> 3) & 1) * 8;
    const int krow_f = lane & 7;        // QK B (non-trans): key row offset
    const int kcol_f = ((lane >> 3) & 1) * 8;

    const int kt_lo = (qt >= WINDOW - 1) ? qt - (WINDOW - 1) : 0;

    // ---- issue V chunk cp.async (1 group) ----
    auto issue_v = [&](int buf, int k0, int c) {
#pragma unroll
        for (int i = 0; i < 4; i++) {
            const int j = tid + i * 256;
            const int row = j >> 4, col8 = (j & 15) * 8;
            cp_async16(sb + (uint32_t)(VPL(buf, 0) + row * PV + col8) * 2,
                       g_Vh + (size_t)(base + k0 + row) * VDIM + c * 128 + col8);
            cp_async16(sb + (uint32_t)(VPL(buf, 1) + row * PV + col8) * 2,
                       g_Vl + (size_t)(base + k0 + row) * VDIM + c * 128 + col8);
        }
        CP_COMMIT();
    };

    issue_v(0, kt_lo * 64, 0);

    // ---- load Q tile once, rebalanced + split ----
#pragma unroll 4
    for (int i = 0; i < 16; i++) {
        const int idx = tid + i * 256;
        const int row = idx >> 6;
        const int c4 = (idx & 63) * 4;
        float4 v = *(const float4*)(g_Q + (size_t)(base + q0 + row) * HEADD + c4);
        const float e = (float)row * (1.0f / 512.0f);
        const float f0 = exp2f(__log2f(((float)c4 + 102.4f) * (1.0f / 358.4f)) * e + 6.0f);
        const float f1 = exp2f(__log2f(((float)c4 + 104.4f) * (1.0f / 358.4f)) * e + 6.0f);
        __half h0, l0, h1, l1, h2, l2, h3, l3;
        hsplit(v.x * f0, h0, l0); hsplit(v.y * f0, h1, l1);
        hsplit(v.z * f1, h2, l2); hsplit(v.w * f1, h3, l3);
        __half* ph = sm + OFF_QH + row * QP + c4;
        __half* pl = sm + OFF_QL + row * QP + c4;
        *(__half2*)(ph) = __halves2half2(h0, h1);  *(__half2*)(ph + 2) = __halves2half2(h2, h3);
        *(__half2*)(pl) = __halves2half2(l0, l1);  *(__half2*)(pl + 2) = __halves2half2(l2, l3);
    }

    float o[2][16][4];
#pragma unroll
    for (int a = 0; a < 2; a++)
#pragma unroll
        for (int n = 0; n < 16; n++)
#pragma unroll
            for (int c = 0; c < 4; c++) o[a][n][c] = 0.0f;

    for (int kt = kt_lo; kt <= qt; kt++) {
        const int k0 = kt * 64;

        // ---- load K tile, rebalanced + split ----
#pragma unroll 4
        for (int i = 0; i < 16; i++) {
            const int idx = tid + i * 256;
            const int row = idx >> 6;
            const int c4 = (idx & 63) * 4;
            float4 v = *(const float4*)(g_K + (size_t)(base + k0 + row) * HEADD + c4);
            const float e = (float)(q0 - (k0 + row)) * (1.0f / 512.0f);
            const float f0 = exp2f(__log2f(((float)c4 + 102.4f) * (1.0f / 358.4f)) * e + 6.0f);
            const float f1 = exp2f(__log2f(((float)c4 + 104.4f) * (1.0f / 358.4f)) * e + 6.0f);
            __half h0, l0, h1, l1, h2, l2, h3, l3;
            hsplit(v.x * f0, h0, l0); hsplit(v.y * f0, h1, l1);
            hsplit(v.z * f1, h2, l2); hsplit(v.w * f1, h3, l3);
            __half* ph = sm + OFF_KH + row * QP + c4;
            __half* pl = sm + OFF_KL + row * QP + c4;
            *(__half2*)(ph) = __halves2half2(h0, h1);  *(__half2*)(ph + 2) = __halves2half2(h2, h3);
            *(__half2*)(pl) = __halves2half2(l0, l1);  *(__half2*)(pl + 2) = __halves2half2(l2, l3);
        }
        __syncthreads();

        // ---- QK: S = Q̃ @ K̃^T over d=256 ----
        float s4[2][2][4];
#pragma unroll
        for (int a = 0; a < 2; a++)
#pragma unroll
            for (int n = 0; n < 2; n++)
#pragma unroll
                for (int c = 0; c < 4; c++) s4[a][n][c] = 0.0f;

#pragma unroll 4
        for (int ks = 0; ks < 16; ks++) {
            const int kk = ks * 16;
            uint32_t ah[2][4], al[2][4], bh[2][2], bl[2][2];
#pragma unroll
            for (int mf = 0; mf < 2; mf++) {
                const uint32_t off = (uint32_t)((wm + mf * 16 + arow_f) * QP + kk + acol_f) * 2;
                ldm_x4(ah[mf], sb + (uint32_t)OFF_QH * 2 + off);
                ldm_x4(al[mf], sb + (uint32_t)OFF_QL * 2 + off);
            }
#pragma unroll
            for (int nf = 0; nf < 2; nf++) {
                const uint32_t off = (uint32_t)((wn + nf * 8 + krow_f) * QP + kk + kcol_f) * 2;
                ldm_x2(bh[nf], sb + (uint32_t)OFF_KH * 2 + off);
                ldm_x2(bl[nf], sb + (uint32_t)OFF_KL * 2 + off);
            }
#pragma unroll
            for (int mf = 0; mf < 2; mf++)
#pragma unroll
                for (int nf = 0; nf < 2; nf++)
                    mma3(s4[mf][nf], ah[mf], al[mf], bh[nf], bl[nf]);
        }

        // ---- decay + split S into fp16 planes ----
        if (kt < qt) {
#pragma unroll
            for (int mf = 0; mf < 2; mf++) {
                const int q_l = wm + mf * 16 + g;
                const int dq0 = (q0 - k0) + q_l - (wn + 2 * tg);
                const float d00 = exp2f((float)dq0 * LOG2_GAMMA);
#pragma unroll
                for (int nf = 0; nf < 2; nf++) {
                    const int k_l = wn + nf * 8 + 2 * tg;
                    const float dc0 = (nf == 0) ? d00 : d00 * GAMMA_M8;
                    const float dc1 = dc0 * GAMMA_INV;
                    const float dc2 = dc0 * GAMMA_P8;
                    const float dc3 = dc2 * GAMMA_INV;
                    __half h0, l0, h1, l1;
                    hsplit(s4[mf][nf][0] * dc0, h0, l0);
                    hsplit(s4[mf][nf][1] * dc1, h1, l1);
                    *(__half2*)(sm + OFF_SH + q_l * PS + k_l) = __halves2half2(h0, h1);
                    *(__half2*)(sm + OFF_SL + q_l * PS + k_l) = __halves2half2(l0, l1);
                    hsplit(s4[mf][nf][2] * dc2, h0, l0);
                    hsplit(s4[mf][nf][3] * dc3, h1, l1);
                    *(__half2*)(sm + OFF_SH + (q_l + 8) * PS + k_l) = __halves2half2(h0, h1);
                    *(__half2*)(sm + OFF_SL + (q_l + 8) * PS + k_l) = __halves2half2(l0, l1);
                }
            }
        } else {
#pragma unroll
            for (int mf = 0; mf < 2; mf++) {
                const int q_l = wm + mf * 16 + g;
#pragma unroll
                for (int nf = 0; nf < 2; nf++) {
                    const int k_l = wn + nf * 8 + 2 * tg;
#pragma unroll
                    for (int c = 0; c < 4; c += 2) {
                        const int qq = q_l + (c >> 1) * 8;
                        __half h0, l0, h1, l1;
                        const int d0 = qq - k_l;
                        const float dec0 = (d0 >= 0) ? exp2f((float)d0 * LOG2_GAMMA) : 0.0f;
                        const float dec1 = (d0 - 1 >= 0) ? dec0 * GAMMA_INV : 0.0f;
                        hsplit(s4[mf][nf][c] * dec0, h0, l0);
                        hsplit(s4[mf][nf][c + 1] * dec1, h1, l1);
                        *(__half2*)(sm + OFF_SH + qq * PS + k_l) = __halves2half2(h0, h1);
                        *(__half2*)(sm + OFF_SL + qq * PS + k_l) = __halves2half2(l0, l1);
                    }
                }
            }
        }
        __syncthreads();

        // ---- PV over 4 chunks of 128 v-cols, double-buffered cp.async ----
        for (int c = 0; c < 4; c++) {
            const bool last = (kt == qt) && (c == 3);
            if (!last) {
                if (c < 3) issue_v((c + 1) & 1, k0, c + 1);
                else       issue_v(0, k0 + 64, 0);
                CP_WAIT(1);
            } else {
                CP_WAIT(0);
            }
            __syncthreads();

            const int vbuf = c & 1;
#pragma unroll
            for (int ks = 0; ks < 4; ks++) {
                const int kk = ks * 16;
                uint32_t ah[2][4], al[2][4], bh[4][2], bl[4][2];
#pragma unroll
                for (int mf = 0; mf < 2; mf++) {
                    const uint32_t off = (uint32_t)((wm + mf * 16 + arow_f) * PS + kk + acol_f) * 2;
                    ldm_x4(ah[mf], sb + (uint32_t)OFF_SH * 2 + off);
                    ldm_x4(al[mf], sb + (uint32_t)OFF_SL * 2 + off);
                }
#pragma unroll
                for (int nf = 0; nf < 4; nf++) {
                    const uint32_t off = (uint32_t)((kk + brow_f) * PV + wvc + nf * 8) * 2;
                    ldm_x2t(bh[nf], sb + (uint32_t)VPL(vbuf, 0) * 2 + off);
                    ldm_x2t(bl[nf], sb + (uint32_t)VPL(vbuf, 1) * 2 + off);
                }
#pragma unroll
                for (int mf = 0; mf < 2; mf++)
#pragma unroll
                    for (int nf = 0; nf < 4; nf++)
                        mma3(o[mf][c * 4 + nf], ah[mf], al[mf], bh[nf], bl[nf]);
            }
            __syncthreads();
        }
    }

    // ---- store O ----
    const float inv = 1.0f / 262144.0f;   // 64 (Q) * 64 (K) * 64 (V)
#pragma unroll
    for (int mf = 0; mf < 2; mf++) {
        const int q_l = wm + mf * 16 + g;
#pragma unroll
        for (int c = 0; c < 4; c++)
#pragma unroll
            for (int nf = 0; nf < 4; nf++) {
                const int v = c * 128 + wvc + nf * 8 + 2 * tg;
                const size_t r0 = (size_t)(base + q0 + q_l) * VDIM + v;
                float* oo = o[mf][c * 4 + nf];
                *(float2*)&Out[r0]            = make_float2(oo[0] * inv, oo[1] * inv);
                *(float2*)&Out[r0 + 8 * VDIM] = make_float2(oo[2] * inv, oo[3] * inv);
            }
    }
}

// ===========================================================================
extern "C" void kernel_launch(void* const* d_in, const int* in_sizes, int n_in,
                              void* d_out, int out_size)
{
    const float* X  = (const float*)d_in[0];
    const float* WQ = (const float*)d_in[1];
    const float* WK = (const float*)d_in[2];
    const float* WV = (const float*)d_in[3];
    float* out = (float*)d_out;

    cudaFuncSetAttribute(proj_kernel, cudaFuncAttributeMaxDynamicSharedMemorySize, PROJ_SMEM);
    cudaFuncSetAttribute(retention_kernel, cudaFuncAttributeMaxDynamicSharedMemorySize, RET_SMEM);

    proj_kernel<<<dim3(8, MROWS / 128), 256, PROJ_SMEM>>>(X, WQ, WK, WV);
    retention_kernel<<<dim3(SEQ / 64, BATCH), 256, RET_SMEM>>>(out);
}